// round 5
// baseline (speedup 1.0000x reference)
#include <cuda_runtime.h>
#include <cstdint>

// Problem constants: b=1, n=4 views, f=8 frames, l=256, C=320, H=8, D=40.
#define C       320
#define L       1024
#define H       8
#define D       40
#define BFRM    8
#define ROWS    (BFRM * L)   // 8192

// ---- scratch (no allocations allowed) ----
__device__ float g_Q   [ROWS * C];
__device__ float g_K   [ROWS * C];
__device__ float g_V   [ROWS * C];
__device__ float g_Qi  [ROWS * C];
__device__ float g_base[ROWS * C];
__device__ float g_iat [ROWS * C];
__device__ float g_W2  [C * C];
__device__ float g_b2  [C];

// logical row (bf*1024 + n*256 + l) -> hidden row ((n*8+bf)*256 + l)
__device__ __forceinline__ int hidden_row(int g) {
    int bf = g >> 10;
    int r  = g & 1023;
    int n  = r >> 8;
    int l  = r & 255;
    return ((n << 3) + bf) * 256 + l;
}

// ============================================================================
// tf32 helpers
// ============================================================================
__device__ __forceinline__ uint32_t tf32_of(float x) {
    uint32_t r;
    asm("cvt.rna.tf32.f32 %0, %1;" : "=r"(r) : "f"(x));
    return r;
}

__device__ __forceinline__ void mma8(float d[4],
                                     const uint32_t a[4],
                                     uint32_t b0, uint32_t b1) {
    asm volatile(
        "mma.sync.aligned.m16n8k8.row.col.f32.tf32.tf32.f32 "
        "{%0,%1,%2,%3}, {%4,%5,%6,%7}, {%8,%9}, {%0,%1,%2,%3};"
        : "+f"(d[0]), "+f"(d[1]), "+f"(d[2]), "+f"(d[3])
        : "r"(a[0]), "r"(a[1]), "r"(a[2]), "r"(a[3]), "r"(b0), "r"(b1));
}

__device__ __forceinline__ void mma8r(float d[4],
                                      uint32_t a0, uint32_t a1, uint32_t a2, uint32_t a3,
                                      uint32_t b0, uint32_t b1) {
    asm volatile(
        "mma.sync.aligned.m16n8k8.row.col.f32.tf32.tf32.f32 "
        "{%0,%1,%2,%3}, {%4,%5,%6,%7}, {%8,%9}, {%0,%1,%2,%3};"
        : "+f"(d[0]), "+f"(d[1]), "+f"(d[2]), "+f"(d[3])
        : "r"(a0), "r"(a1), "r"(a2), "r"(a3), "r"(b0), "r"(b1));
}

// ============================================================================
// 3xTF32 GEMM core: 128x64 block tile, 8 warps (4x2) of 32x32, K-block 16.
// A/B split into tf32 hi/lo at smem fill; fragments bank-conflict-free.
// ============================================================================
#define ASTR 20
#define BSTR 72

struct GemmSmem {
    float Ah[128][ASTR];
    float Al[128][ASTR];
    float Bh[16][BSTR];
    float Bl[16][BSTR];
};

__device__ __forceinline__ void split_store(float x, float* hi, float* lo) {
    uint32_t hb = tf32_of(x);
    float hf = __uint_as_float(hb);
    *hi = hf;
    *lo = __uint_as_float(tf32_of(x - hf));
}

// load one 128x16 A tile (rows contiguous from Asrc) + 16x64 B tile into smem
__device__ __forceinline__ void gemm_load_tile(
    GemmSmem& S, const float* __restrict__ Asrc, const float* __restrict__ Bsrc,
    int k0, int n0, int t)
{
    int lrow = t >> 1, lkc = (t & 1) * 8;
    const float* ap = Asrc + (size_t)lrow * C + k0 + lkc;
    float4 u = *(const float4*)ap;
    float4 v = *(const float4*)(ap + 4);
    split_store(u.x, &S.Ah[lrow][lkc + 0], &S.Al[lrow][lkc + 0]);
    split_store(u.y, &S.Ah[lrow][lkc + 1], &S.Al[lrow][lkc + 1]);
    split_store(u.z, &S.Ah[lrow][lkc + 2], &S.Al[lrow][lkc + 2]);
    split_store(u.w, &S.Ah[lrow][lkc + 3], &S.Al[lrow][lkc + 3]);
    split_store(v.x, &S.Ah[lrow][lkc + 4], &S.Al[lrow][lkc + 4]);
    split_store(v.y, &S.Ah[lrow][lkc + 5], &S.Al[lrow][lkc + 5]);
    split_store(v.z, &S.Ah[lrow][lkc + 6], &S.Al[lrow][lkc + 6]);
    split_store(v.w, &S.Ah[lrow][lkc + 7], &S.Al[lrow][lkc + 7]);
    int brow = t >> 4, bcol = (t & 15) * 4;
    float4 bv = *(const float4*)(Bsrc + (size_t)(k0 + brow) * C + n0 + bcol);
    split_store(bv.x, &S.Bh[brow][bcol + 0], &S.Bl[brow][bcol + 0]);
    split_store(bv.y, &S.Bh[brow][bcol + 1], &S.Bl[brow][bcol + 1]);
    split_store(bv.z, &S.Bh[brow][bcol + 2], &S.Bl[brow][bcol + 2]);
    split_store(bv.w, &S.Bh[brow][bcol + 3], &S.Bl[brow][bcol + 3]);
}

// one K-block (two k8 steps) of 3xTF32 mma into acc[2][4][4]
__device__ __forceinline__ void gemm_mma_tile(
    GemmSmem& S, float acc[2][4][4], int wm, int wn, int g, int tig)
{
#pragma unroll
    for (int ks = 0; ks < 2; ks++) {
        const int kk = ks * 8;
        uint32_t ah[2][4], al[2][4];
#pragma unroll
        for (int mb = 0; mb < 2; mb++) {
            int r = wm + mb * 16 + g;
            ah[mb][0] = __float_as_uint(S.Ah[r    ][kk + tig]);
            ah[mb][1] = __float_as_uint(S.Ah[r + 8][kk + tig]);
            ah[mb][2] = __float_as_uint(S.Ah[r    ][kk + tig + 4]);
            ah[mb][3] = __float_as_uint(S.Ah[r + 8][kk + tig + 4]);
            al[mb][0] = __float_as_uint(S.Al[r    ][kk + tig]);
            al[mb][1] = __float_as_uint(S.Al[r + 8][kk + tig]);
            al[mb][2] = __float_as_uint(S.Al[r    ][kk + tig + 4]);
            al[mb][3] = __float_as_uint(S.Al[r + 8][kk + tig + 4]);
        }
#pragma unroll
        for (int nb = 0; nb < 4; nb++) {
            int cn = wn + nb * 8 + g;
            uint32_t b0h = __float_as_uint(S.Bh[kk + tig    ][cn]);
            uint32_t b1h = __float_as_uint(S.Bh[kk + tig + 4][cn]);
            uint32_t b0l = __float_as_uint(S.Bl[kk + tig    ][cn]);
            uint32_t b1l = __float_as_uint(S.Bl[kk + tig + 4][cn]);
#pragma unroll
            for (int mb = 0; mb < 2; mb++) {
                mma8(acc[mb][nb], ah[mb], b0h, b1h);
                mma8(acc[mb][nb], ah[mb], b0l, b1l);
                mma8(acc[mb][nb], al[mb], b0h, b1h);
            }
        }
    }
}

// ============================================================================
// Kernel 1: projections via 3xTF32 tensor cores.
// z selects {Wq->g_Q, Wk->g_K(tf32), Wv->g_V(tf32), Wqi->g_Qi}.
// ============================================================================
__global__ __launch_bounds__(256) void proj_mma_kernel(
    const float* __restrict__ hidden,
    const float* __restrict__ Wq, const float* __restrict__ Wk,
    const float* __restrict__ Wv, const float* __restrict__ Wqi)
{
    const float* Wm; float* Y; bool rnd = false;
    switch (blockIdx.z) {
        case 0:  Wm = Wq;  Y = g_Q;  break;
        case 1:  Wm = Wk;  Y = g_K;  rnd = true; break;
        case 2:  Wm = Wv;  Y = g_V;  rnd = true; break;
        default: Wm = Wqi; Y = g_Qi; break;
    }
    __shared__ GemmSmem S;
    const int t = threadIdx.x, w = t >> 5, lane = t & 31;
    const int g = lane >> 2, tig = lane & 3;
    const int m0 = blockIdx.x * 128, n0 = blockIdx.y * 64;
    const int wm = (w & 3) * 32, wn = (w >> 2) * 32;
    const float* Asrc = hidden + (size_t)hidden_row(m0) * C;  // rows contiguous

    float acc[2][4][4];
#pragma unroll
    for (int mb = 0; mb < 2; mb++)
#pragma unroll
        for (int nb = 0; nb < 4; nb++)
#pragma unroll
            for (int e = 0; e < 4; e++) acc[mb][nb][e] = 0.f;

    for (int k0 = 0; k0 < C; k0 += 16) {
        __syncthreads();
        gemm_load_tile(S, Asrc, Wm, k0, n0, t);
        __syncthreads();
        gemm_mma_tile(S, acc, wm, wn, g, tig);
    }

#pragma unroll
    for (int mb = 0; mb < 2; mb++)
#pragma unroll
        for (int nb = 0; nb < 4; nb++) {
            int r  = m0 + wm + mb * 16 + g;
            int cn = n0 + wn + nb * 8 + 2 * tig;
            float4 d = *(float4*)acc[mb][nb];
            if (rnd) {
                d.x = __uint_as_float(tf32_of(d.x));
                d.y = __uint_as_float(tf32_of(d.y));
                d.z = __uint_as_float(tf32_of(d.z));
                d.w = __uint_as_float(tf32_of(d.w));
            }
            *(float2*)&Y[(size_t)r * C + cn]       = make_float2(d.x, d.y);
            *(float2*)&Y[(size_t)(r + 8) * C + cn] = make_float2(d.z, d.w);
        }
}

// ============================================================================
// Kernel 2: flash attention, single-pass tf32 mma (unchanged from R2).
// ============================================================================
#define KT        64
#define QT        64
#define KV_STRIDE 44
#define P_STRIDE  66
#define SMEM_KV   (KT * KV_STRIDE)
#define SMEM_ATTN ((2 * SMEM_KV + 4 * 16 * P_STRIDE) * 4)

__global__ __launch_bounds__(128) void attn_mma_kernel()
{
    extern __shared__ float sm[];
    const int i2v = blockIdx.z >> 3;
    const int bf  = blockIdx.z & 7;
    const int h   = blockIdx.y;
    const int qt  = blockIdx.x;

    const float* Qsrc = i2v ? g_Qi : g_Q;
    float*       O    = i2v ? g_iat : g_base;
    const int kvbase  = i2v ? 0 : bf * L;

    const int tid  = threadIdx.x;
    const int w    = tid >> 5;
    const int lane = tid & 31;
    const int g    = lane >> 2;
    const int tig  = lane & 3;

    float* Ks = sm;
    float* Vs = Ks + SMEM_KV;
    float* Pw = Vs + SMEM_KV + w * (16 * P_STRIDE);

    const int qrow0 = bf * L + qt * QT + w * 16;
    const float scale = 0.15811388300841897f;
    uint32_t qa[5][4];
#pragma unroll
    for (int ks = 0; ks < 5; ks++) {
#pragma unroll
        for (int e = 0; e < 4; e++) {
            int r = g + ((e & 1) ? 8 : 0);
            int c = 8 * ks + tig + ((e & 2) ? 4 : 0);
            float x = Qsrc[(size_t)(qrow0 + r) * C + h * D + c] * scale;
            qa[ks][e] = tf32_of(x);
        }
    }

    float mrow0 = -1e30f, mrow1 = -1e30f;
    float lrow0 = 0.f,    lrow1 = 0.f;
    float o[5][4];
#pragma unroll
    for (int n = 0; n < 5; n++)
#pragma unroll
        for (int e = 0; e < 4; e++) o[n][e] = 0.f;

    for (int kt = 0; kt < L / KT; kt++) {
        __syncthreads();
        {
            const float* Kg = g_K + (size_t)(kvbase + kt * KT) * C + h * D;
            const float* Vg = g_V + (size_t)(kvbase + kt * KT) * C + h * D;
            for (int e = tid; e < 640; e += 128) {
                int r  = e / 10;
                int c4 = (e - r * 10) * 4;
                int off = r * KV_STRIDE + c4;
                *(float4*)(Ks + off) = *(const float4*)(Kg + (size_t)r * C + c4);
                *(float4*)(Vs + off) = *(const float4*)(Vg + (size_t)r * C + c4);
            }
        }
        __syncthreads();

        float s[8][4];
#pragma unroll
        for (int n = 0; n < 8; n++) {
            s[n][0] = s[n][1] = s[n][2] = s[n][3] = 0.f;
            const int key = n * 8 + g;
            const float* kp = Ks + key * KV_STRIDE + tig;
#pragma unroll
            for (int ks = 0; ks < 5; ks++) {
                uint32_t b0 = __float_as_uint(kp[8 * ks]);
                uint32_t b1 = __float_as_uint(kp[8 * ks + 4]);
                mma8r(s[n], qa[ks][0], qa[ks][1], qa[ks][2], qa[ks][3], b0, b1);
            }
        }

        float tmax0 = -1e30f, tmax1 = -1e30f;
#pragma unroll
        for (int n = 0; n < 8; n++) {
            tmax0 = fmaxf(tmax0, fmaxf(s[n][0], s[n][1]));
            tmax1 = fmaxf(tmax1, fmaxf(s[n][2], s[n][3]));
        }
        tmax0 = fmaxf(tmax0, __shfl_xor_sync(0xffffffff, tmax0, 1));
        tmax0 = fmaxf(tmax0, __shfl_xor_sync(0xffffffff, tmax0, 2));
        tmax1 = fmaxf(tmax1, __shfl_xor_sync(0xffffffff, tmax1, 1));
        tmax1 = fmaxf(tmax1, __shfl_xor_sync(0xffffffff, tmax1, 2));

        float mn0 = fmaxf(mrow0, tmax0);
        float mn1 = fmaxf(mrow1, tmax1);
        float corr0 = __expf(mrow0 - mn0);
        float corr1 = __expf(mrow1 - mn1);
        mrow0 = mn0; mrow1 = mn1;
        lrow0 *= corr0; lrow1 *= corr1;
#pragma unroll
        for (int n = 0; n < 5; n++) {
            o[n][0] *= corr0; o[n][1] *= corr0;
            o[n][2] *= corr1; o[n][3] *= corr1;
        }

        __syncwarp();
        float ps0 = 0.f, ps1 = 0.f;
#pragma unroll
        for (int n = 0; n < 8; n++) {
            float p0 = __expf(s[n][0] - mn0);
            float p1 = __expf(s[n][1] - mn0);
            float p2 = __expf(s[n][2] - mn1);
            float p3 = __expf(s[n][3] - mn1);
            ps0 += p0 + p1;
            ps1 += p2 + p3;
            p0 = __uint_as_float(tf32_of(p0));
            p1 = __uint_as_float(tf32_of(p1));
            p2 = __uint_as_float(tf32_of(p2));
            p3 = __uint_as_float(tf32_of(p3));
            *(float2*)&Pw[g * P_STRIDE + 8 * n + 2 * tig]       = make_float2(p0, p1);
            *(float2*)&Pw[(g + 8) * P_STRIDE + 8 * n + 2 * tig] = make_float2(p2, p3);
        }
        ps0 += __shfl_xor_sync(0xffffffff, ps0, 1);
        ps0 += __shfl_xor_sync(0xffffffff, ps0, 2);
        ps1 += __shfl_xor_sync(0xffffffff, ps1, 1);
        ps1 += __shfl_xor_sync(0xffffffff, ps1, 2);
        lrow0 += ps0; lrow1 += ps1;
        __syncwarp();

#pragma unroll
        for (int ks2 = 0; ks2 < 8; ks2++) {
            uint32_t a0 = __float_as_uint(Pw[g * P_STRIDE + 8 * ks2 + tig]);
            uint32_t a1 = __float_as_uint(Pw[(g + 8) * P_STRIDE + 8 * ks2 + tig]);
            uint32_t a2 = __float_as_uint(Pw[g * P_STRIDE + 8 * ks2 + tig + 4]);
            uint32_t a3 = __float_as_uint(Pw[(g + 8) * P_STRIDE + 8 * ks2 + tig + 4]);
            const float* vp  = Vs + (8 * ks2 + tig) * KV_STRIDE + g;
            const float* vp4 = Vs + (8 * ks2 + tig + 4) * KV_STRIDE + g;
#pragma unroll
            for (int n = 0; n < 5; n++) {
                uint32_t b0 = __float_as_uint(vp [8 * n]);
                uint32_t b1 = __float_as_uint(vp4[8 * n]);
                mma8r(o[n], a0, a1, a2, a3, b0, b1);
            }
        }
    }

    float inv0 = __fdividef(1.f, lrow0);
    float inv1 = __fdividef(1.f, lrow1);
    float* op0 = O + (size_t)(qrow0 + g)     * C + h * D;
    float* op1 = O + (size_t)(qrow0 + g + 8) * C + h * D;
#pragma unroll
    for (int n = 0; n < 5; n++) {
        *(float2*)(op0 + 8 * n + 2 * tig) = make_float2(o[n][0] * inv0, o[n][1] * inv0);
        *(float2*)(op1 + 8 * n + 2 * tig) = make_float2(o[n][2] * inv1, o[n][3] * inv1);
    }
}

// ============================================================================
// Kernel 3a: W2 = Woi @ Wo (fp32 scalar, 320x320x320 — tiny)
// ============================================================================
__global__ __launch_bounds__(256) void w2_kernel(
    const float* __restrict__ Woi, const float* __restrict__ Wo)
{
    __shared__ float As[16][64];
    __shared__ float Bs[16][64];
    int t  = threadIdx.x;
    int m0 = blockIdx.x * 64, n0 = blockIdx.y * 64;
    int ty = t >> 4, tx = t & 15;
    int am = t >> 2, ak = (t & 3) * 4;
    int nb = t & 63, kb = t >> 6;

    float acc[4][4];
#pragma unroll
    for (int i = 0; i < 4; i++)
#pragma unroll
        for (int j = 0; j < 4; j++) acc[i][j] = 0.f;

    for (int k0 = 0; k0 < C; k0 += 16) {
        float4 av = *(const float4*)(Woi + (size_t)(m0 + am) * C + k0 + ak);
        As[ak][am] = av.x; As[ak + 1][am] = av.y;
        As[ak + 2][am] = av.z; As[ak + 3][am] = av.w;
#pragma unroll
        for (int i = 0; i < 4; i++)
            Bs[kb + 4 * i][nb] = Wo[(size_t)(k0 + kb + 4 * i) * C + n0 + nb];
        __syncthreads();
#pragma unroll
        for (int kk = 0; kk < 16; kk++) {
            float4 a = *(const float4*)&As[kk][ty * 4];
            float4 b = *(const float4*)&Bs[kk][tx * 4];
            acc[0][0] += a.x * b.x; acc[0][1] += a.x * b.y; acc[0][2] += a.x * b.z; acc[0][3] += a.x * b.w;
            acc[1][0] += a.y * b.x; acc[1][1] += a.y * b.y; acc[1][2] += a.y * b.z; acc[1][3] += a.y * b.w;
            acc[2][0] += a.z * b.x; acc[2][1] += a.z * b.y; acc[2][2] += a.z * b.z; acc[2][3] += a.z * b.w;
            acc[3][0] += a.w * b.x; acc[3][1] += a.w * b.y; acc[3][2] += a.w * b.z; acc[3][3] += a.w * b.w;
        }
        __syncthreads();
    }
#pragma unroll
    for (int i = 0; i < 4; i++)
        *(float4*)&g_W2[(size_t)(m0 + ty * 4 + i) * C + n0 + tx * 4] =
            make_float4(acc[i][0], acc[i][1], acc[i][2], acc[i][3]);
}

// Kernel 3b: b2 = boi @ Wo + bo
__global__ __launch_bounds__(320) void b2_kernel(
    const float* __restrict__ boi, const float* __restrict__ Wo,
    const float* __restrict__ bo)
{
    int n = threadIdx.x;
    float s = bo[n];
    for (int k = 0; k < C; k++) s += boi[k] * Wo[(size_t)k * C + n];
    g_b2[n] = s;
}

// ============================================================================
// Kernel 4: fused epilogue. out = base @ Wo + iat @ W2 + b2,
// scattered back to (b n f) l c layout. 3xTF32, K = 640 (two phases).
// ============================================================================
__global__ __launch_bounds__(256) void ep_fused_kernel(
    const float* __restrict__ Wo, float* __restrict__ out)
{
    __shared__ GemmSmem S;
    const int t = threadIdx.x, w = t >> 5, lane = t & 31;
    const int g = lane >> 2, tig = lane & 3;
    const int m0 = blockIdx.x * 128, n0 = blockIdx.y * 64;
    const int wm = (w & 3) * 32, wn = (w >> 2) * 32;

    float acc[2][4][4];
#pragma unroll
    for (int mb = 0; mb < 2; mb++)
#pragma unroll
        for (int nb = 0; nb < 4; nb++)
#pragma unroll
            for (int e = 0; e < 4; e++) acc[mb][nb][e] = 0.f;

    for (int kt = 0; kt < 40; kt++) {
        const bool ph0 = kt < 20;
        const float* Asrc = (ph0 ? g_base : g_iat) + (size_t)m0 * C;
        const float* Bsrc = ph0 ? Wo : g_W2;
        const int k0 = (ph0 ? kt : kt - 20) * 16;
        __syncthreads();
        gemm_load_tile(S, Asrc, Bsrc, k0, n0, t);
        __syncthreads();
        gemm_mma_tile(S, acc, wm, wn, g, tig);
    }

    const int orow0 = hidden_row(m0);   // rows contiguous within a 128-tile
#pragma unroll
    for (int mb = 0; mb < 2; mb++)
#pragma unroll
        for (int nb = 0; nb < 4; nb++) {
            int rl = wm + mb * 16 + g;
            int cn = n0 + wn + nb * 8 + 2 * tig;
            float2 bv = *(const float2*)&g_b2[cn];   // same cols for both rows
            float4 d = *(float4*)acc[mb][nb];
            *(float2*)&out[(size_t)(orow0 + rl) * C + cn] =
                make_float2(d.x + bv.x, d.y + bv.y);
            *(float2*)&out[(size_t)(orow0 + rl + 8) * C + cn] =
                make_float2(d.z + bv.x, d.w + bv.y);
        }
}

// ============================================================================
extern "C" void kernel_launch(void* const* d_in, const int* in_sizes, int n_in,
                              void* d_out, int out_size)
{
    const float* hidden = (const float*)d_in[0];
    const float* Wq  = (const float*)d_in[1];
    const float* Wk  = (const float*)d_in[2];
    const float* Wv  = (const float*)d_in[3];
    const float* Wo  = (const float*)d_in[4];
    const float* bo  = (const float*)d_in[5];
    const float* Wqi = (const float*)d_in[6];
    const float* Woi = (const float*)d_in[7];
    const float* boi = (const float*)d_in[8];
    float* out = (float*)d_out;

    // 0) fold i2v output projection into Wo: W2 = Woi@Wo, b2 = boi@Wo + bo
    w2_kernel<<<dim3(C / 64, C / 64), 256>>>(Woi, Wo);
    b2_kernel<<<1, C>>>(boi, Wo, bo);

    // 1) Q, K, V, Q_i2v projections (3xTF32 tensor cores; K/V tf32-rounded)
    proj_mma_kernel<<<dim3(ROWS / 128, C / 64, 4), 256>>>(hidden, Wq, Wk, Wv, Wqi);

    // 2) both attentions in one launch (z: bf 0-7 = base, 8-15 = i2v)
    cudaFuncSetAttribute(attn_mma_kernel,
                         cudaFuncAttributeMaxDynamicSharedMemorySize, SMEM_ATTN);
    attn_mma_kernel<<<dim3(L / QT, H, 2 * BFRM), 128, SMEM_ATTN>>>();

    // 3) out = base@Wo + iat@W2 + b2 (fused, scattered store)
    ep_fused_kernel<<<dim3(ROWS / 128, C / 64), 256>>>(Wo, out);
}

// round 6
// speedup vs baseline: 1.3941x; 1.3941x over previous
#include <cuda_runtime.h>
#include <cstdint>

// Problem constants: b=1, n=4 views, f=8 frames, l=256, C=320, H=8, D=40.
#define C       320
#define L       1024
#define H       8
#define D       40
#define BFRM    8
#define ROWS    (BFRM * L)   // 8192

// ---- scratch (no allocations allowed) ----
// Q/K/V/Qi stored HEAD-MAJOR: [H][ROWS][D]
__device__ float g_Q   [H * ROWS * D];
__device__ float g_K   [H * ROWS * D];
__device__ float g_V   [H * ROWS * D];
__device__ float g_Qi  [H * ROWS * D];
__device__ float g_base[ROWS * C];   // row-major (GEMM A operand)
__device__ float g_iat [ROWS * C];
__device__ float g_W2  [C * C];
__device__ float g_b2  [C];

// logical row (bf*1024 + n*256 + l) -> hidden row ((n*8+bf)*256 + l)
__device__ __forceinline__ int hidden_row(int g) {
    int bf = g >> 10;
    int r  = g & 1023;
    int n  = r >> 8;
    int l  = r & 255;
    return ((n << 3) + bf) * 256 + l;
}

// ============================================================================
// tf32 helpers
// ============================================================================
__device__ __forceinline__ uint32_t tf32_of(float x) {
    uint32_t r;
    asm("cvt.rna.tf32.f32 %0, %1;" : "=r"(r) : "f"(x));
    return r;
}
__device__ __forceinline__ float tf32f(float x) {
    return __uint_as_float(tf32_of(x));
}

__device__ __forceinline__ void mma8r(float d[4],
                                      uint32_t a0, uint32_t a1, uint32_t a2, uint32_t a3,
                                      uint32_t b0, uint32_t b1) {
    asm volatile(
        "mma.sync.aligned.m16n8k8.row.col.f32.tf32.tf32.f32 "
        "{%0,%1,%2,%3}, {%4,%5,%6,%7}, {%8,%9}, {%0,%1,%2,%3};"
        : "+f"(d[0]), "+f"(d[1]), "+f"(d[2]), "+f"(d[3])
        : "r"(a0), "r"(a1), "r"(a2), "r"(a3), "r"(b0), "r"(b1));
}

// ============================================================================
// Single-pass TF32 GEMM core: 128x64 block tile, 8 warps (4x2) of 32x32,
// K-block 32. Strides chosen for conflict-free fragment LDS.
// ============================================================================
#define KBLK 32
#define ASTR 36
#define BSTR 72

struct GemmSmem {
    float A[128][ASTR];
    float B[KBLK][BSTR];
};

// load one 128x32 A tile (rows contiguous from Asrc, row stride C) and a
// 32x64 B tile, converting to tf32.
__device__ __forceinline__ void gemm_load_tile(
    GemmSmem& S, const float* __restrict__ Asrc, const float* __restrict__ Bsrc,
    int k0, int n0, int t)
{
    const int lrow = t >> 1, abase = (t & 1) * 16;
    const float* ap = Asrc + (size_t)lrow * C + k0 + abase;
#pragma unroll
    for (int i = 0; i < 4; i++) {
        float4 u = *(const float4*)(ap + 4 * i);
        S.A[lrow][abase + 4 * i + 0] = tf32f(u.x);
        S.A[lrow][abase + 4 * i + 1] = tf32f(u.y);
        S.A[lrow][abase + 4 * i + 2] = tf32f(u.z);
        S.A[lrow][abase + 4 * i + 3] = tf32f(u.w);
    }
    const int brow = t >> 3, bbase = (t & 7) * 8;
    const float* bp = Bsrc + (size_t)(k0 + brow) * C + n0 + bbase;
#pragma unroll
    for (int i = 0; i < 2; i++) {
        float4 u = *(const float4*)(bp + 4 * i);
        S.B[brow][bbase + 4 * i + 0] = tf32f(u.x);
        S.B[brow][bbase + 4 * i + 1] = tf32f(u.y);
        S.B[brow][bbase + 4 * i + 2] = tf32f(u.z);
        S.B[brow][bbase + 4 * i + 3] = tf32f(u.w);
    }
}

// one K-block (four k8 steps) of tf32 mma into acc[2][4][4]
__device__ __forceinline__ void gemm_mma_tile(
    GemmSmem& S, float acc[2][4][4], int wm, int wn, int g, int tig)
{
#pragma unroll
    for (int ks = 0; ks < 4; ks++) {
        const int kk = ks * 8;
        uint32_t a[2][4];
#pragma unroll
        for (int mb = 0; mb < 2; mb++) {
            int r = wm + mb * 16 + g;
            a[mb][0] = __float_as_uint(S.A[r    ][kk + tig]);
            a[mb][1] = __float_as_uint(S.A[r + 8][kk + tig]);
            a[mb][2] = __float_as_uint(S.A[r    ][kk + tig + 4]);
            a[mb][3] = __float_as_uint(S.A[r + 8][kk + tig + 4]);
        }
#pragma unroll
        for (int nb = 0; nb < 4; nb++) {
            int cn = wn + nb * 8 + g;
            uint32_t b0 = __float_as_uint(S.B[kk + tig    ][cn]);
            uint32_t b1 = __float_as_uint(S.B[kk + tig + 4][cn]);
#pragma unroll
            for (int mb = 0; mb < 2; mb++)
                mma8r(acc[mb][nb], a[mb][0], a[mb][1], a[mb][2], a[mb][3], b0, b1);
        }
    }
}

// ============================================================================
// Kernel 1: projections via tf32 tensor cores, writing HEAD-MAJOR outputs.
// z selects {Wq->g_Q, Wk->g_K, Wv->g_V, Wqi->g_Qi}.
// ============================================================================
__global__ __launch_bounds__(256) void proj_mma_kernel(
    const float* __restrict__ hidden,
    const float* __restrict__ Wq, const float* __restrict__ Wk,
    const float* __restrict__ Wv, const float* __restrict__ Wqi)
{
    const float* Wm; float* Y;
    switch (blockIdx.z) {
        case 0:  Wm = Wq;  Y = g_Q;  break;
        case 1:  Wm = Wk;  Y = g_K;  break;
        case 2:  Wm = Wv;  Y = g_V;  break;
        default: Wm = Wqi; Y = g_Qi; break;
    }
    __shared__ GemmSmem S;
    const int t = threadIdx.x, w = t >> 5, lane = t & 31;
    const int g = lane >> 2, tig = lane & 3;
    const int m0 = blockIdx.x * 128, n0 = blockIdx.y * 64;
    const int wm = (w & 3) * 32, wn = (w >> 2) * 32;
    const float* Asrc = hidden + (size_t)hidden_row(m0) * C;  // rows contiguous

    float acc[2][4][4];
#pragma unroll
    for (int mb = 0; mb < 2; mb++)
#pragma unroll
        for (int nb = 0; nb < 4; nb++)
#pragma unroll
            for (int e = 0; e < 4; e++) acc[mb][nb][e] = 0.f;

    for (int k0 = 0; k0 < C; k0 += KBLK) {
        __syncthreads();
        gemm_load_tile(S, Asrc, Wm, k0, n0, t);
        __syncthreads();
        gemm_mma_tile(S, acc, wm, wn, g, tig);
    }

    // head-major scatter: column cn -> head cn/40, offset cn%40.
    // cn is even and 40 is even, so a float2 never crosses a head boundary.
#pragma unroll
    for (int mb = 0; mb < 2; mb++)
#pragma unroll
        for (int nb = 0; nb < 4; nb++) {
            int r  = m0 + wm + mb * 16 + g;
            int cn = n0 + wn + nb * 8 + 2 * tig;
            int h  = cn / D, c = cn - h * D;
            float4 d = *(float4*)acc[mb][nb];
            float* base = Y + ((size_t)h * ROWS) * D + c;
            *(float2*)&base[(size_t)r * D]       = make_float2(d.x, d.y);
            *(float2*)&base[(size_t)(r + 8) * D] = make_float2(d.z, d.w);
        }
}

// ============================================================================
// Kernel 2: flash attention, single-pass tf32 mma, head-major K/V (coalesced
// tile loads). One launch covers base (i2v=0) and i2v (i2v=1).
// ============================================================================
#define KT        64
#define QT        64
#define KV_STRIDE 44
#define P_STRIDE  66
#define SMEM_KV   (KT * KV_STRIDE)
#define SMEM_ATTN ((2 * SMEM_KV + 4 * 16 * P_STRIDE) * 4)

__global__ __launch_bounds__(128) void attn_mma_kernel()
{
    extern __shared__ float sm[];
    const int i2v = blockIdx.z >> 3;
    const int bf  = blockIdx.z & 7;
    const int h   = blockIdx.y;
    const int qt  = blockIdx.x;

    const float* Qsrc = (i2v ? g_Qi : g_Q) + (size_t)h * ROWS * D;
    const float* Khd  = g_K + (size_t)h * ROWS * D;
    const float* Vhd  = g_V + (size_t)h * ROWS * D;
    float*       O    = i2v ? g_iat : g_base;
    const int kvbase  = i2v ? 0 : bf * L;

    const int tid  = threadIdx.x;
    const int w    = tid >> 5;
    const int lane = tid & 31;
    const int g    = lane >> 2;
    const int tig  = lane & 3;

    float* Ks = sm;
    float* Vs = Ks + SMEM_KV;
    float* Pw = Vs + SMEM_KV + w * (16 * P_STRIDE);

    const int qrow0 = bf * L + qt * QT + w * 16;
    const float scale = 0.15811388300841897f;
    uint32_t qa[5][4];
#pragma unroll
    for (int ks = 0; ks < 5; ks++) {
#pragma unroll
        for (int e = 0; e < 4; e++) {
            int r = g + ((e & 1) ? 8 : 0);
            int c = 8 * ks + tig + ((e & 2) ? 4 : 0);
            float x = Qsrc[(size_t)(qrow0 + r) * D + c] * scale;
            qa[ks][e] = tf32_of(x);
        }
    }

    float mrow0 = -1e30f, mrow1 = -1e30f;
    float lrow0 = 0.f,    lrow1 = 0.f;
    float o[5][4];
#pragma unroll
    for (int n = 0; n < 5; n++)
#pragma unroll
        for (int e = 0; e < 4; e++) o[n][e] = 0.f;

    for (int kt = 0; kt < L / KT; kt++) {
        __syncthreads();
        {
            // fully contiguous 64x40-float tile (10240 B each for K and V)
            const float4* Kg = (const float4*)(Khd + (size_t)(kvbase + kt * KT) * D);
            const float4* Vg = (const float4*)(Vhd + (size_t)(kvbase + kt * KT) * D);
#pragma unroll
            for (int f = tid; f < 640; f += 128) {
                int r  = f / 10;
                int c4 = (f - r * 10) * 4;
                int off = r * KV_STRIDE + c4;
                *(float4*)(Ks + off) = Kg[f];
                *(float4*)(Vs + off) = Vg[f];
            }
        }
        __syncthreads();

        float s[8][4];
#pragma unroll
        for (int n = 0; n < 8; n++) {
            s[n][0] = s[n][1] = s[n][2] = s[n][3] = 0.f;
            const int key = n * 8 + g;
            const float* kp = Ks + key * KV_STRIDE + tig;
#pragma unroll
            for (int ks = 0; ks < 5; ks++) {
                uint32_t b0 = __float_as_uint(kp[8 * ks]);
                uint32_t b1 = __float_as_uint(kp[8 * ks + 4]);
                mma8r(s[n], qa[ks][0], qa[ks][1], qa[ks][2], qa[ks][3], b0, b1);
            }
        }

        float tmax0 = -1e30f, tmax1 = -1e30f;
#pragma unroll
        for (int n = 0; n < 8; n++) {
            tmax0 = fmaxf(tmax0, fmaxf(s[n][0], s[n][1]));
            tmax1 = fmaxf(tmax1, fmaxf(s[n][2], s[n][3]));
        }
        tmax0 = fmaxf(tmax0, __shfl_xor_sync(0xffffffff, tmax0, 1));
        tmax0 = fmaxf(tmax0, __shfl_xor_sync(0xffffffff, tmax0, 2));
        tmax1 = fmaxf(tmax1, __shfl_xor_sync(0xffffffff, tmax1, 1));
        tmax1 = fmaxf(tmax1, __shfl_xor_sync(0xffffffff, tmax1, 2));

        float mn0 = fmaxf(mrow0, tmax0);
        float mn1 = fmaxf(mrow1, tmax1);
        float corr0 = __expf(mrow0 - mn0);
        float corr1 = __expf(mrow1 - mn1);
        mrow0 = mn0; mrow1 = mn1;
        lrow0 *= corr0; lrow1 *= corr1;
#pragma unroll
        for (int n = 0; n < 5; n++) {
            o[n][0] *= corr0; o[n][1] *= corr0;
            o[n][2] *= corr1; o[n][3] *= corr1;
        }

        __syncwarp();
        float ps0 = 0.f, ps1 = 0.f;
#pragma unroll
        for (int n = 0; n < 8; n++) {
            float p0 = __expf(s[n][0] - mn0);
            float p1 = __expf(s[n][1] - mn0);
            float p2 = __expf(s[n][2] - mn1);
            float p3 = __expf(s[n][3] - mn1);
            ps0 += p0 + p1;
            ps1 += p2 + p3;
            p0 = tf32f(p0); p1 = tf32f(p1); p2 = tf32f(p2); p3 = tf32f(p3);
            *(float2*)&Pw[g * P_STRIDE + 8 * n + 2 * tig]       = make_float2(p0, p1);
            *(float2*)&Pw[(g + 8) * P_STRIDE + 8 * n + 2 * tig] = make_float2(p2, p3);
        }
        ps0 += __shfl_xor_sync(0xffffffff, ps0, 1);
        ps0 += __shfl_xor_sync(0xffffffff, ps0, 2);
        ps1 += __shfl_xor_sync(0xffffffff, ps1, 1);
        ps1 += __shfl_xor_sync(0xffffffff, ps1, 2);
        lrow0 += ps0; lrow1 += ps1;
        __syncwarp();

#pragma unroll
        for (int ks2 = 0; ks2 < 8; ks2++) {
            uint32_t a0 = __float_as_uint(Pw[g * P_STRIDE + 8 * ks2 + tig]);
            uint32_t a1 = __float_as_uint(Pw[(g + 8) * P_STRIDE + 8 * ks2 + tig]);
            uint32_t a2 = __float_as_uint(Pw[g * P_STRIDE + 8 * ks2 + tig + 4]);
            uint32_t a3 = __float_as_uint(Pw[(g + 8) * P_STRIDE + 8 * ks2 + tig + 4]);
            const float* vp  = Vs + (8 * ks2 + tig) * KV_STRIDE + g;
            const float* vp4 = Vs + (8 * ks2 + tig + 4) * KV_STRIDE + g;
#pragma unroll
            for (int n = 0; n < 5; n++) {
                uint32_t b0 = __float_as_uint(vp [8 * n]);
                uint32_t b1 = __float_as_uint(vp4[8 * n]);
                mma8r(o[n], a0, a1, a2, a3, b0, b1);
            }
        }
    }

    float inv0 = __fdividef(1.f, lrow0);
    float inv1 = __fdividef(1.f, lrow1);
    float* op0 = O + (size_t)(qrow0 + g)     * C + h * D;
    float* op1 = O + (size_t)(qrow0 + g + 8) * C + h * D;
#pragma unroll
    for (int n = 0; n < 5; n++) {
        *(float2*)(op0 + 8 * n + 2 * tig) = make_float2(o[n][0] * inv0, o[n][1] * inv0);
        *(float2*)(op1 + 8 * n + 2 * tig) = make_float2(o[n][2] * inv1, o[n][3] * inv1);
    }
}

// ============================================================================
// Kernel 3a: W2 = Woi @ Wo (fp32 scalar, tiny)
// ============================================================================
__global__ __launch_bounds__(256) void w2_kernel(
    const float* __restrict__ Woi, const float* __restrict__ Wo)
{
    __shared__ float As[16][64];
    __shared__ float Bs[16][64];
    int t  = threadIdx.x;
    int m0 = blockIdx.x * 64, n0 = blockIdx.y * 64;
    int ty = t >> 4, tx = t & 15;
    int am = t >> 2, ak = (t & 3) * 4;
    int nb = t & 63, kb = t >> 6;

    float acc[4][4];
#pragma unroll
    for (int i = 0; i < 4; i++)
#pragma unroll
        for (int j = 0; j < 4; j++) acc[i][j] = 0.f;

    for (int k0 = 0; k0 < C; k0 += 16) {
        float4 av = *(const float4*)(Woi + (size_t)(m0 + am) * C + k0 + ak);
        As[ak][am] = av.x; As[ak + 1][am] = av.y;
        As[ak + 2][am] = av.z; As[ak + 3][am] = av.w;
#pragma unroll
        for (int i = 0; i < 4; i++)
            Bs[kb + 4 * i][nb] = Wo[(size_t)(k0 + kb + 4 * i) * C + n0 + nb];
        __syncthreads();
#pragma unroll
        for (int kk = 0; kk < 16; kk++) {
            float4 a = *(const float4*)&As[kk][ty * 4];
            float4 b = *(const float4*)&Bs[kk][tx * 4];
            acc[0][0] += a.x * b.x; acc[0][1] += a.x * b.y; acc[0][2] += a.x * b.z; acc[0][3] += a.x * b.w;
            acc[1][0] += a.y * b.x; acc[1][1] += a.y * b.y; acc[1][2] += a.y * b.z; acc[1][3] += a.y * b.w;
            acc[2][0] += a.z * b.x; acc[2][1] += a.z * b.y; acc[2][2] += a.z * b.z; acc[2][3] += a.z * b.w;
            acc[3][0] += a.w * b.x; acc[3][1] += a.w * b.y; acc[3][2] += a.w * b.z; acc[3][3] += a.w * b.w;
        }
        __syncthreads();
    }
#pragma unroll
    for (int i = 0; i < 4; i++)
        *(float4*)&g_W2[(size_t)(m0 + ty * 4 + i) * C + n0 + tx * 4] =
            make_float4(acc[i][0], acc[i][1], acc[i][2], acc[i][3]);
}

// Kernel 3b: b2 = boi @ Wo + bo
__global__ __launch_bounds__(320) void b2_kernel(
    const float* __restrict__ boi, const float* __restrict__ Wo,
    const float* __restrict__ bo)
{
    int n = threadIdx.x;
    float s = bo[n];
    for (int k = 0; k < C; k++) s += boi[k] * Wo[(size_t)k * C + n];
    g_b2[n] = s;
}

// ============================================================================
// Kernel 4: fused epilogue. out = base @ Wo + iat @ W2 + b2,
// scattered back to (b n f) l c layout. Single-pass tf32, K = 640.
// ============================================================================
__global__ __launch_bounds__(256) void ep_fused_kernel(
    const float* __restrict__ Wo, float* __restrict__ out)
{
    __shared__ GemmSmem S;
    const int t = threadIdx.x, w = t >> 5, lane = t & 31;
    const int g = lane >> 2, tig = lane & 3;
    const int m0 = blockIdx.x * 128, n0 = blockIdx.y * 64;
    const int wm = (w & 3) * 32, wn = (w >> 2) * 32;

    float acc[2][4][4];
#pragma unroll
    for (int mb = 0; mb < 2; mb++)
#pragma unroll
        for (int nb = 0; nb < 4; nb++)
#pragma unroll
            for (int e = 0; e < 4; e++) acc[mb][nb][e] = 0.f;

    for (int kt = 0; kt < 20; kt++) {
        const bool ph0 = kt < 10;
        const float* Asrc = (ph0 ? g_base : g_iat) + (size_t)m0 * C;
        const float* Bsrc = ph0 ? Wo : g_W2;
        const int k0 = (ph0 ? kt : kt - 10) * KBLK;
        __syncthreads();
        gemm_load_tile(S, Asrc, Bsrc, k0, n0, t);
        __syncthreads();
        gemm_mma_tile(S, acc, wm, wn, g, tig);
    }

    const int orow0 = hidden_row(m0);   // rows contiguous within a 128-tile
#pragma unroll
    for (int mb = 0; mb < 2; mb++)
#pragma unroll
        for (int nb = 0; nb < 4; nb++) {
            int rl = wm + mb * 16 + g;
            int cn = n0 + wn + nb * 8 + 2 * tig;
            float2 bv = *(const float2*)&g_b2[cn];   // same cols for both rows
            float4 d = *(float4*)acc[mb][nb];
            *(float2*)&out[(size_t)(orow0 + rl) * C + cn] =
                make_float2(d.x + bv.x, d.y + bv.y);
            *(float2*)&out[(size_t)(orow0 + rl + 8) * C + cn] =
                make_float2(d.z + bv.x, d.w + bv.y);
        }
}

// ============================================================================
extern "C" void kernel_launch(void* const* d_in, const int* in_sizes, int n_in,
                              void* d_out, int out_size)
{
    const float* hidden = (const float*)d_in[0];
    const float* Wq  = (const float*)d_in[1];
    const float* Wk  = (const float*)d_in[2];
    const float* Wv  = (const float*)d_in[3];
    const float* Wo  = (const float*)d_in[4];
    const float* bo  = (const float*)d_in[5];
    const float* Wqi = (const float*)d_in[6];
    const float* Woi = (const float*)d_in[7];
    const float* boi = (const float*)d_in[8];
    float* out = (float*)d_out;

    // 0) fold i2v output projection into Wo: W2 = Woi@Wo, b2 = boi@Wo + bo
    w2_kernel<<<dim3(C / 64, C / 64), 256>>>(Woi, Wo);
    b2_kernel<<<1, C>>>(boi, Wo, bo);

    // 1) Q, K, V, Q_i2v projections (tf32 tensor cores, head-major outputs)
    proj_mma_kernel<<<dim3(ROWS / 128, C / 64, 4), 256>>>(hidden, Wq, Wk, Wv, Wqi);

    // 2) both attentions in one launch (z: bf 0-7 = base, 8-15 = i2v)
    cudaFuncSetAttribute(attn_mma_kernel,
                         cudaFuncAttributeMaxDynamicSharedMemorySize, SMEM_ATTN);
    attn_mma_kernel<<<dim3(L / QT, H, 2 * BFRM), 128, SMEM_ATTN>>>();

    // 3) out = base@Wo + iat@W2 + b2 (fused, scattered store)
    ep_fused_kernel<<<dim3(ROWS / 128, C / 64), 256>>>(Wo, out);
}